// round 4
// baseline (speedup 1.0000x reference)
#include <cuda_runtime.h>
#include <cstdint>

// out[b,c,h,w] = x[b,c,2h,2w] * 0.5f     (Haar DWT subband sum collapses to this)
// x:  [16, 64, 512, 512] fp32,  out: [16, 64, 256, 256] fp32
//
// Each thread handles 8 consecutive output floats (one "unit"):
//   4 independent float4 loads from an even input row (64B, MLP=4)
//   2 float4 stores (STG.128) to the output row.
//
// Geometry (powers of two):
//   output row = 256 floats = 32 units     -> u    = i & 31
//   256 output rows                        -> orow = (i >> 5) & 255
//   1024 fused batch*channel               -> bc   = i >> 13
//   input float4/row = 128; even row 2*orow -> row float4 base = orow*256
//   input float4 base = bc*65536 + orow*256 + u*4

__global__ __launch_bounds__(256) void haar_sum_kernel(
    const float4* __restrict__ x, float4* __restrict__ out)
{
    unsigned i = blockIdx.x * blockDim.x + threadIdx.x;   // unit index, < 2^23

    unsigned u    = i & 31u;
    unsigned orow = (i >> 5) & 255u;
    unsigned bc   = i >> 13;

    long long in_base = ((long long)bc << 16) + ((long long)orow << 8) + ((long long)u << 2);

    // 4 independent streaming loads — front-batched for MLP
    float4 v0 = __ldcs(&x[in_base + 0]);
    float4 v1 = __ldcs(&x[in_base + 1]);
    float4 v2 = __ldcs(&x[in_base + 2]);
    float4 v3 = __ldcs(&x[in_base + 3]);

    float4 o0, o1;
    o0.x = v0.x * 0.5f;  o0.y = v0.z * 0.5f;
    o0.z = v1.x * 0.5f;  o0.w = v1.z * 0.5f;
    o1.x = v2.x * 0.5f;  o1.y = v2.z * 0.5f;
    o1.z = v3.x * 0.5f;  o1.w = v3.z * 0.5f;

    long long out_base = (long long)i * 2;
    __stcs(&out[out_base + 0], o0);
    __stcs(&out[out_base + 1], o1);
}

extern "C" void kernel_launch(void* const* d_in, const int* in_sizes, int n_in,
                              void* d_out, int out_size)
{
    const float4* x = (const float4*)d_in[0];
    float4* out     = (float4*)d_out;

    // out_size = 67,108,864 floats -> 8,388,608 units of 8 floats
    long long n_units = (long long)out_size / 8;
    const int threads = 256;
    long long blocks = (n_units + threads - 1) / threads;   // 32768

    haar_sum_kernel<<<(unsigned)blocks, threads>>>(x, out);
}

// round 5
// speedup vs baseline: 1.1591x; 1.1591x over previous
#include <cuda_runtime.h>
#include <cstdint>

// out[b,c,h,w] = x[b,c,2h,2w] * 0.5f     (Haar DWT subband sum collapses to this)
// x:  [16, 64, 512, 512] fp32,  out: [16, 64, 256, 256] fp32
//
// Geometry identical to the R2 kernel (fully warp-coalesced):
//   pair index p in [0, 33'554'432):  out float2 index = p
//   pair  = p & 127          (128 float2 per output row)
//   orow  = (p >> 7) & 255
//   bc    = p >> 15
//   input float4 index = bc*65536 + orow*256 + pair   (even row 2*orow)
//
// MLP=2: each block owns 512 consecutive pairs; thread t processes
// pairs base+t and base+256+t. Both LDG.128 are 512B-contiguous per warp,
// both STG.64 coalesced. Loads front-batched for memory-level parallelism.

__device__ __forceinline__ long long pair_to_in_idx(unsigned p)
{
    unsigned pair = p & 127u;
    unsigned orow = (p >> 7) & 255u;
    unsigned bc   = p >> 15;
    return ((long long)bc << 16) + ((long long)orow << 8) + pair;
}

__global__ __launch_bounds__(256) void haar_sum_kernel(
    const float4* __restrict__ x, float2* __restrict__ out)
{
    unsigned i0 = blockIdx.x * 512u + threadIdx.x;   // first pair
    unsigned i1 = i0 + 256u;                          // second pair

    long long a0 = pair_to_in_idx(i0);
    long long a1 = pair_to_in_idx(i1);

    // two independent streaming loads in flight
    float4 v0 = __ldcs(&x[a0]);
    float4 v1 = __ldcs(&x[a1]);

    float2 o0, o1;
    o0.x = v0.x * 0.5f;  o0.y = v0.z * 0.5f;
    o1.x = v1.x * 0.5f;  o1.y = v1.z * 0.5f;

    __stcs(&out[i0], o0);
    __stcs(&out[i1], o1);
}

extern "C" void kernel_launch(void* const* d_in, const int* in_sizes, int n_in,
                              void* d_out, int out_size)
{
    const float4* x = (const float4*)d_in[0];
    float2* out     = (float2*)d_out;

    // out_size = 67,108,864 floats -> 33,554,432 pairs -> 512 pairs per block
    long long n_pairs = (long long)out_size / 2;
    long long blocks  = n_pairs / 512;                 // 65536

    haar_sum_kernel<<<(unsigned)blocks, 256>>>(x, out);
}